// round 4
// baseline (speedup 1.0000x reference)
#include <cuda_runtime.h>
#include <cuda_fp16.h>

// Problem constants
#define BB   4
#define CC   12
#define HH   256
#define WW   256
#define HWSZ 65536                 // H*W
#define NPIX (BB*HWSZ)             // 262144
#define NBC  (BB*CC)               // 48
#define NPLANE (2*NBC)             // 96 masks (48 pred + 48 target)
#define SENT 30000                 // column sentinel: SENT^2 = 9e8 >> 130050 max real candidate
#define NCOLGRP 4                  // column groups per plane in k_col
#define COLTHR (WW/NCOLGRP)        // 64 threads per k_col block
#define PSTRIDE 32                 // doubles between per-plane accumulators (256B anti-contention)

// ---------------- scratch (static __device__ — no allocation) ----------------
__device__ unsigned char d_code[NPIX];    // pred: argmax class if pmax>0.5 else 255
__device__ unsigned char d_tcode[NPIX];   // target class byte
__device__ __half d_err2[NBC * HWSZ];     // (softmax - onehot)^2 per (b,c,pixel)
__device__ short d_g[NPLANE * HWSZ];      // signed column dist: sign = mask bit, |v| = dist to opposite polarity
__device__ int   d_hasfg[NPLANE];
__device__ int   d_hasbg[NPLANE];
__device__ double d_pacc[NPLANE * PSTRIDE]; // per-plane loss partials (spread to kill atomic serialization)
__device__ double d_ce;                   // CE sum
__device__ int   d_is64;                  // target serialized as int64?

// ---------------- helpers ----------------
__device__ __forceinline__ float blockReduceSum(float v) {
    __shared__ float s[32];
    int lane = threadIdx.x & 31, wid = threadIdx.x >> 5;
    #pragma unroll
    for (int o = 16; o; o >>= 1) v += __shfl_down_sync(0xFFFFFFFFu, v, o);
    if (lane == 0) s[wid] = v;
    __syncthreads();
    v = (threadIdx.x < (blockDim.x >> 5)) ? s[lane] : 0.f;
    if (wid == 0) {
        #pragma unroll
        for (int o = 16; o; o >>= 1) v += __shfl_down_sync(0xFFFFFFFFu, v, o);
    }
    return v;
}

// ---------------- 1) init: zero accumulators/flags + detect target dtype ----------------
__global__ void k_init(const void* __restrict__ tgt) {
    __shared__ int bad;
    if (threadIdx.x == 0) { bad = 0; d_ce = 0.0; }
    __syncthreads();
    for (int i = threadIdx.x; i < NPLANE * PSTRIDE; i += 256) d_pacc[i] = 0.0;
    for (int i = threadIdx.x; i < NPLANE; i += 256) { d_hasfg[i] = 0; d_hasbg[i] = 0; }
    // int64 targets (values 0..11) have all-zero high words; int32 serialization
    // would put real targets (~0 chance all zero) in those slots.
    const int* t32 = (const int*)tgt;
    int any = 0;
    for (int i = threadIdx.x; i < 4096; i += 256)
        if (t32[2 * i + 1] != 0) any = 1;
    if (any) atomicOr(&bad, 1);
    __syncthreads();
    if (threadIdx.x == 0) d_is64 = (bad == 0) ? 1 : 0;
}

// ---------------- 2) prep: softmax -> codes, err2 planes (fp16), CE partial ----------------
__global__ void k_prep(const float* __restrict__ pred, const void* __restrict__ tgt) {
    int p  = blockIdx.x * 256 + threadIdx.x;   // pixel index (b,hw)
    int b  = p >> 16;
    int hw = p & 65535;
    const float* base = pred + (size_t)b * CC * HWSZ + hw;

    float x[CC];
    #pragma unroll
    for (int c = 0; c < CC; c++) x[c] = base[(size_t)c * HWSZ];

    float m = x[0]; int am = 0;
    #pragma unroll
    for (int c = 1; c < CC; c++) if (x[c] > m) { m = x[c]; am = c; }

    float e[CC], s = 0.f;
    #pragma unroll
    for (int c = 0; c < CC; c++) { e[c] = expf(x[c] - m); s += e[c]; }
    float inv = 1.f / s;

    // pmax = 1/s ; pmax > 0.5 <=> s < 2. Only the argmax class can exceed 0.5.
    d_code[p] = (s < 2.0f) ? (unsigned char)am : (unsigned char)255;

    int t = d_is64 ? (int)((const long long*)tgt)[p] : ((const int*)tgt)[p];
    d_tcode[p] = (unsigned char)t;

    float xt = 0.f;                            // predicated selects: no dynamic reg-array index
    #pragma unroll
    for (int c = 0; c < CC; c++) if (c == t) xt = x[c];

    #pragma unroll
    for (int c = 0; c < CC; c++) {
        float er = e[c] * inv - ((c == t) ? 1.f : 0.f);
        d_err2[(size_t)(b * CC + c) * HWSZ + hw] = __float2half(er * er);
    }

    float ce = -(xt - m - logf(s));
    float r = blockReduceSum(ce);
    if (threadIdx.x == 0) atomicAdd(&d_ce, (double)r);
}

// ---------------- 3) column pass: signed 1D distance to opposite polarity along H ----------------
// Each thread owns one column; forward distances staged in smem (no global RMW).
__global__ void k_col() {
    __shared__ short sfwd[HH * COLTHR];        // [h][tid], 32KB; thread-private columns, no sync
    int bid   = blockIdx.x;
    int plane = bid / NCOLGRP;
    int grp   = bid % NCOLGRP;
    int tid   = threadIdx.x;
    int w     = grp * COLTHR + tid;
    int st = plane / NBC;                      // 0 = pred masks, 1 = target masks
    int b  = (plane % NBC) / CC;
    int c  = plane % CC;

    const unsigned char* code = (st ? d_tcode : d_code) + b * HWSZ;
    size_t pbase = (size_t)plane * HWSZ;

    unsigned mb[8];
    #pragma unroll
    for (int i = 0; i < 8; i++) mb[i] = 0;

    // forward sweep: distance to nearest opposite-polarity pixel above
    int run = SENT, prev = -1;
    for (int h = 0; h < HH; h++) {
        int mv = (code[h * WW + w] == c);
        mb[h >> 5] |= (unsigned)mv << (h & 31);
        if (prev >= 0) run = (mv != prev) ? 1 : min(run + 1, SENT);
        sfwd[h * COLTHR + tid] = (short)run;
        prev = mv;
    }

    // backward sweep: combine with forward, sign-encode mask bit, single global write
    run = SENT; prev = -1;
    for (int h = HH - 1; h >= 0; h--) {
        int mv = (mb[h >> 5] >> (h & 31)) & 1;
        if (prev >= 0) run = (mv != prev) ? 1 : min(run + 1, SENT);
        int d = min(run, (int)sfwd[h * COLTHR + tid]);
        d_g[pbase + h * WW + w] = (short)(mv ? d : -d);
        prev = mv;
    }

    int fg = 0, bg = 0;
    #pragma unroll
    for (int i = 0; i < 8; i++) {
        if (mb[i]) fg = 1;
        if (mb[i] != 0xFFFFFFFFu) bg = 1;
    }
    unsigned afg = __ballot_sync(0xFFFFFFFFu, fg);
    unsigned abg = __ballot_sync(0xFFFFFFFFu, bg);
    if ((tid & 31) == 0) {
        if (afg) atomicOr(&d_hasfg[plane], 1);
        if (abg) atomicOr(&d_hasbg[plane], 1);
    }
}

// ---------------- 4) row pass: exact 2D squared EDT (unified search) + fused loss ----------------
// For pixel j, the trivial-polarity field term is 0, so:
//   D2[j] = min_j' S[j'] + (j-j')^2,  S = own-polarity squared column field.
// Expanding radius is exact: r^2 >= best implies every candidate at radius >= r loses.
__global__ void k_row() {
    int bid   = blockIdx.x;
    int plane = bid >> 8;
    int h     = bid & 255;
    if (!d_hasfg[plane]) return;               // reference zeroes the field for empty masks

    __shared__ float sA[WW], sB[WW];           // A-query field (mask pixels), B-query field (bg pixels)
    int j = threadIdx.x;
    size_t base = (size_t)plane * HWSZ + (size_t)h * WW;
    float v  = (float)d_g[base + j];
    float v2 = v * v;
    sA[j] = (v > 0.f) ? v2 : 0.f;              // sA[j'] = g2 toward bg at mask px, 0 at bg px
    sB[j] = (v > 0.f) ? 0.f : v2;              // sB[j'] = g2 toward mask at bg px, 0 at mask px
    __syncthreads();

    int hasbg = d_hasbg[plane];                // plane-uniform
    float best;
    if (hasbg) {
        const float* S = (v > 0.f) ? sA : sB;
        best = v2;                             // own candidate (r = 0)
        for (int r = 1; r < WW; r++) {
            float rr = (float)(r * r);
            if (rr >= best) break;
            int jl = j - r, jr = j + r;
            if (jl >= 0) best = fminf(best, S[jl] + rr);
            if (jr < WW) best = fminf(best, S[jr] + rr);
        }
    } else {
        best = 1.0e12f;                        // mask all-true: edt(mask)=1e6 everywhere, field^2=1e12
    }

    float e2 = __half2float(d_err2[(size_t)(plane % NBC) * HWSZ + (size_t)h * WW + j]);
    float r = blockReduceSum(e2 * best);
    if (threadIdx.x == 0) atomicAdd(&d_pacc[plane * PSTRIDE], (double)r);
}

// ---------------- 5) finalize scalar ----------------
__global__ void k_fin(float* __restrict__ out) {
    __shared__ double sd[NPLANE];
    int t = threadIdx.x;
    if (t < NPLANE) sd[t] = d_pacc[t * PSTRIDE];
    __syncthreads();
    if (t == 0) {
        double s = 0.0;
        #pragma unroll
        for (int i = 0; i < NPLANE; i++) s += sd[i];
        // loss_sum = s / (B*H*W); out = loss_sum/C/B/3 + ce_mean
        out[0] = (float)(s / (262144.0 * 144.0) + d_ce / 262144.0);
    }
}

// ---------------- launch ----------------
extern "C" void kernel_launch(void* const* d_in, const int* in_sizes, int n_in,
                              void* d_out, int out_size) {
    const float* pred = (const float*)d_in[0];
    const void*  tgt  = d_in[1];
    float* out = (float*)d_out;

    k_init<<<1, 256>>>(tgt);
    k_prep<<<NPIX / 256, 256>>>(pred, tgt);
    k_col <<<NPLANE * NCOLGRP, COLTHR>>>();
    k_row <<<NPLANE * HH, 256>>>();
    k_fin <<<1, 128>>>(out);
}

// round 16
// speedup vs baseline: 1.0370x; 1.0370x over previous
#include <cuda_runtime.h>
#include <cuda_fp16.h>

// Problem constants
#define BB   4
#define CC   12
#define HH   256
#define WW   256
#define HWSZ 65536                 // H*W
#define NPIX (BB*HWSZ)             // 262144
#define NBC  (BB*CC)               // 48
#define NPLANE (2*NBC)             // 96 masks (planes 0..47 pred, 48..95 target)
#define SENT 30000                 // column sentinel
#define NCOLGRP 8
#define COLTHR (WW/NCOLGRP)        // 32 columns per pred-column block
#define NPCOLB (NBC*NCOLGRP)       // 384 pred-column blocks
#define PSTRIDE 32                 // doubles between per-plane accumulators
#define NPREPB (NPIX/256)          // 1024 prep blocks

// ---------------- scratch (static __device__ — no allocation) ----------------
__device__ unsigned char d_code[NPIX];    // pred: argmax class if pmax>0.5 else 255
__device__ __half d_err2[NBC * HWSZ];     // (softmax - onehot)^2
__device__ short d_g[NPLANE * HWSZ];      // signed column dist: sign = mask bit, |v| = dist to opposite
__device__ int   d_hasfg[NPLANE];         // static zero-init; re-zeroed by k_fin each run
__device__ int   d_hasbg[NPLANE];
__device__ double d_pacc[NPLANE * PSTRIDE];
__device__ double d_ce;

// ---------------- helpers ----------------
__device__ __forceinline__ float blockReduceSum(float v) {
    __shared__ float s[32];
    int lane = threadIdx.x & 31, wid = threadIdx.x >> 5;
    #pragma unroll
    for (int o = 16; o; o >>= 1) v += __shfl_down_sync(0xFFFFFFFFu, v, o);
    if (lane == 0) s[wid] = v;
    __syncthreads();
    v = (threadIdx.x < (blockDim.x >> 5)) ? s[lane] : 0.f;
    if (wid == 0) {
        #pragma unroll
        for (int o = 16; o; o >>= 1) v += __shfl_down_sync(0xFFFFFFFFu, v, o);
    }
    return v;
}

// Per-block target-dtype detection: sample the first 256 int64-high-word slots
// (indices 1,3,..,511 — in-bounds for both int32 and int64 layouts).
// int64 targets (0..11) have zero high words; an int32 layout puts real targets
// there (P(all 256 == 0) = (1/12)^256 ~ 0). Block-uniform result.
__device__ __forceinline__ int detect_is64(const void* tgt) {
    int hi = ((const int*)tgt)[2 * threadIdx.x + 1];
    return !__syncthreads_or(hi != 0);
}

// ---------------- row pass core: exact squared EDT via padded expanding search ----------------
// D2[j] = min_j' S[j'] + (j-j')^2 over own-polarity field S (other polarity term is 0).
// Exact early exit: rr >= best implies all candidates at radius >= r lose.
__device__ __forceinline__ void row_loss(int plane, int h, float* sA, float* sB) {
    int j = threadIdx.x;
    size_t base = (size_t)plane * HWSZ + (size_t)h * WW;
    float v  = (float)d_g[base + j];
    float v2 = v * v;
    __half e2h = d_err2[(size_t)(plane % NBC) * HWSZ + (size_t)h * WW + j];  // prefetch

    sA[j] = 1.0e12f;  sA[2 * WW + j] = 1.0e12f;   // +inf padding both sides
    sB[j] = 1.0e12f;  sB[2 * WW + j] = 1.0e12f;
    int fgpix = (v > 0.f);
    sA[WW + j] = fgpix ? v2 : 0.f;                // mask-pixel queries scan sA
    sB[WW + j] = fgpix ? 0.f : v2;                // bg-pixel queries scan sB
    __syncthreads();

    float best;
    if (d_hasbg[plane]) {
        const float* S = (fgpix ? sA : sB) + WW + j;
        best = v2;                                // r = 0 candidate (own column value)
        int r = 1;
        #pragma unroll 1
        while (true) {
            float rr1 = (float)(r * r);
            if (rr1 >= best) break;
            float c1 = fminf(S[-r], S[r]) + rr1;
            int r2 = r + 1;
            float rr2 = (float)(r2 * r2);
            float c2 = fminf(S[-r2], S[r2]) + rr2;
            best = fminf(best, fminf(c1, c2));
            r += 2;
            if (r >= WW) break;
        }
    } else {
        best = 1.0e12f;                           // mask all-true: field^2 = (1e6)^2 exactly
    }

    float rsum = blockReduceSum(__half2float(e2h) * best);
    if (threadIdx.x == 0) atomicAdd(&d_pacc[plane * PSTRIDE], (double)rsum);
}

// ---------------- 1) merged: softmax/err2/CE (blocks <NPREPB) ∥ target-plane columns ----------------
__global__ void k_prep(const float* __restrict__ pred, const void* __restrict__ tgt) {
    int blk = blockIdx.x;
    int is64 = detect_is64(tgt);
    if (blk < NPREPB) {
        // ---- prep path: one pixel per thread ----
        int p  = blk * 256 + threadIdx.x;
        int b  = p >> 16;
        int hw = p & 65535;
        const float* base = pred + (size_t)b * CC * HWSZ + hw;

        float x[CC];
        #pragma unroll
        for (int c = 0; c < CC; c++) x[c] = base[(size_t)c * HWSZ];

        float m = x[0]; int am = 0;
        #pragma unroll
        for (int c = 1; c < CC; c++) if (x[c] > m) { m = x[c]; am = c; }

        float e[CC], s = 0.f;
        #pragma unroll
        for (int c = 0; c < CC; c++) { e[c] = __expf(x[c] - m); s += e[c]; }
        float inv = __frcp_rn(s);

        // pmax = 1/s > 0.5 <=> s < 2; only the argmax class can exceed 0.5
        d_code[p] = (s < 2.0f) ? (unsigned char)am : (unsigned char)255;

        int t = is64 ? (int)((const long long*)tgt)[p] : ((const int*)tgt)[p];

        float xt = 0.f;
        #pragma unroll
        for (int c = 0; c < CC; c++) if (c == t) xt = x[c];

        #pragma unroll
        for (int c = 0; c < CC; c++) {
            float er = e[c] * inv - ((c == t) ? 1.f : 0.f);
            d_err2[(size_t)(b * CC + c) * HWSZ + hw] = __float2half(er * er);
        }

        float ce = -(xt - m - __logf(s));
        float r = blockReduceSum(ce);
        if (threadIdx.x == 0) atomicAdd(&d_ce, (double)r);
    } else {
        // ---- target-column path: one plane per block, one column per thread (global RMW) ----
        int pt = blk - NPREPB;                 // 0..47
        int plane = NBC + pt;                  // 48..95
        int b = pt / CC, c = pt % CC;
        int w = threadIdx.x;
        size_t tb = (size_t)b * HWSZ;
        size_t pbase = (size_t)plane * HWSZ;

        unsigned mb[8];
        #pragma unroll
        for (int i = 0; i < 8; i++) mb[i] = 0;

        int run = SENT, prev = -1;
        for (int h = 0; h < HH; h++) {
            int idx = h * WW + w;
            int tv = is64 ? (int)((const long long*)tgt)[tb + idx] : ((const int*)tgt)[tb + idx];
            int mv = (tv == c);
            mb[h >> 5] |= (unsigned)mv << (h & 31);
            if (prev >= 0) run = (mv != prev) ? 1 : min(run + 1, SENT);
            d_g[pbase + idx] = (short)run;
            prev = mv;
        }
        run = SENT; prev = -1;
        for (int h = HH - 1; h >= 0; h--) {
            int idx = h * WW + w;
            int mv = (mb[h >> 5] >> (h & 31)) & 1;
            if (prev >= 0) run = (mv != prev) ? 1 : min(run + 1, SENT);
            int d = min(run, (int)d_g[pbase + idx]);
            d_g[pbase + idx] = (short)(mv ? d : -d);
            prev = mv;
        }

        int fg = 0, bg = 0;
        #pragma unroll
        for (int i = 0; i < 8; i++) {
            if (mb[i]) fg = 1;
            if (mb[i] != 0xFFFFFFFFu) bg = 1;
        }
        unsigned afg = __ballot_sync(0xFFFFFFFFu, fg);
        unsigned abg = __ballot_sync(0xFFFFFFFFu, bg);
        if ((w & 31) == 0) {
            if (afg) atomicOr(&d_hasfg[plane], 1);
            if (abg) atomicOr(&d_hasbg[plane], 1);
        }
    }
}

// ---------------- 2) merged: pred-plane columns (blocks <NPCOLB) ∥ target-plane rows ----------------
// Union smem = 16KB -> row blocks are thread-limited (8 blocks/SM, 100% occ).
__global__ void k_mid() {
    __shared__ __align__(16) char su[HH * COLTHR * 2];   // 16KB union
    int bid = blockIdx.x;
    if (bid < NPCOLB) {
        // ---- pred-column path: 32 active threads (1 warp), thread-private smem columns ----
        if (threadIdx.x >= COLTHR) return;
        short* sfwd = (short*)su;
        int plane = bid / NCOLGRP;             // 0..47
        int grp   = bid % NCOLGRP;
        int tid   = threadIdx.x;
        int w     = grp * COLTHR + tid;
        int b  = plane / CC;
        int c  = plane % CC;

        const unsigned char* code = d_code + b * HWSZ;
        size_t pbase = (size_t)plane * HWSZ;

        unsigned mb[8];
        #pragma unroll
        for (int i = 0; i < 8; i++) mb[i] = 0;

        int run = SENT, prev = -1;
        for (int h = 0; h < HH; h++) {
            int mv = (code[h * WW + w] == c);
            mb[h >> 5] |= (unsigned)mv << (h & 31);
            if (prev >= 0) run = (mv != prev) ? 1 : min(run + 1, SENT);
            sfwd[h * COLTHR + tid] = (short)run;
            prev = mv;
        }
        run = SENT; prev = -1;
        for (int h = HH - 1; h >= 0; h--) {
            int mv = (mb[h >> 5] >> (h & 31)) & 1;
            if (prev >= 0) run = (mv != prev) ? 1 : min(run + 1, SENT);
            int d = min(run, (int)sfwd[h * COLTHR + tid]);
            d_g[pbase + h * WW + w] = (short)(mv ? d : -d);
            prev = mv;
        }

        int fg = 0, bg = 0;
        #pragma unroll
        for (int i = 0; i < 8; i++) {
            if (mb[i]) fg = 1;
            if (mb[i] != 0xFFFFFFFFu) bg = 1;
        }
        unsigned afg = __ballot_sync(0xFFFFFFFFu, fg);
        unsigned abg = __ballot_sync(0xFFFFFFFFu, bg);
        if (tid == 0) {
            if (afg) atomicOr(&d_hasfg[plane], 1);
            if (abg) atomicOr(&d_hasbg[plane], 1);
        }
    } else {
        // ---- target-plane row path (columns for these planes computed in k_prep) ----
        int rb    = bid - NPCOLB;
        int plane = NBC + (rb >> 8);           // 48..95
        int h     = rb & 255;
        if (!d_hasfg[plane]) return;           // reference zeroes field for empty masks
        float* sA = (float*)su;                // 3KB
        float* sB = sA + 3 * WW;               // 3KB
        row_loss(plane, h, sA, sB);
    }
}

// ---------------- 3) pred-plane rows (needs k_mid's columns) ----------------
__global__ void k_rowP() {
    int bid   = blockIdx.x;
    int plane = bid >> 8;                      // 0..47
    int h     = bid & 255;
    if (!d_hasfg[plane]) return;
    __shared__ float sA[3 * WW], sB[3 * WW];   // 6KB
    row_loss(plane, h, sA, sB);
}

// ---------------- 4) finalize + restore zero state for next graph replay ----------------
__global__ void k_fin(float* __restrict__ out) {
    __shared__ double sd[NPLANE];
    int t = threadIdx.x;
    if (t < NPLANE) sd[t] = d_pacc[t * PSTRIDE];
    __syncthreads();
    if (t == 0) {
        double s = 0.0;
        #pragma unroll
        for (int i = 0; i < NPLANE; i++) s += sd[i];
        // loss_sum = s / (B*H*W); out = loss_sum/C/B/3 + ce_mean
        out[0] = (float)(s / (262144.0 * 144.0) + d_ce / 262144.0);
        d_ce = 0.0;
    }
    // re-zero accumulators/flags (already consumed above; deterministic across replays)
    for (int i = t; i < NPLANE * PSTRIDE; i += 128) d_pacc[i] = 0.0;
    for (int i = t; i < NPLANE; i += 128) { d_hasfg[i] = 0; d_hasbg[i] = 0; }
}

// ---------------- launch ----------------
extern "C" void kernel_launch(void* const* d_in, const int* in_sizes, int n_in,
                              void* d_out, int out_size) {
    const float* pred = (const float*)d_in[0];
    const void*  tgt  = d_in[1];
    float* out = (float*)d_out;

    k_prep<<<NPREPB + NBC, 256>>>(pred, tgt);      // softmax/err2/CE ∥ target columns
    k_mid <<<NPCOLB + NBC * HH, 256>>>();          // pred columns ∥ target rows
    k_rowP<<<NBC * HH, 256>>>();                   // pred rows
    k_fin <<<1, 128>>>(out);
}